// round 1
// baseline (speedup 1.0000x reference)
#include <cuda_runtime.h>
#include <cuda_bf16.h>
#include <math.h>

// Problem constants
#define H   1024
#define H2  2048
#define H3  3072
#define S   4096
#define V   50257

// Output layout (tuple order: output[V], context[H], new_hidden[2H], attn_w[S])
#define OUT_LOGP 0
#define OUT_CTX  (V)
#define OUT_NEWH (V + H)
#define OUT_ATTN (V + 3 * H)

// Logits kernel geometry
#define LOG_ROWS_PER_BLK 8
#define NB_LOGITS ((V + LOG_ROWS_PER_BLK - 1) / LOG_ROWS_PER_BLK)   // 6283

// ---------------- scratch (device globals; no allocation allowed) -----------
__device__ float g_gi0[H3], g_gh0[H3];
__device__ float g_gi1[H3], g_gh1[H3];
__device__ float g_h1[H];
__device__ float g_v[H];
__device__ float g_ctx[H];
__device__ float g_energ[S];
__device__ float g_attn[S];
__device__ float g_logits[V + 16];
__device__ float g_pm[NB_LOGITS + 16], g_ps[NB_LOGITS + 16];
__device__ float g_red[2];

// ---------------- helpers ---------------------------------------------------
__device__ __forceinline__ float sigm(float x) { return 1.0f / (1.0f + expf(-x)); }

// GRU combine for element j: gates gi/gh are length 3H, hprev length H
__device__ __forceinline__ float gru_combine(const float* gi, const float* gh,
                                             const float* hprev, int j) {
    float r = sigm(gi[j] + gh[j]);
    float z = sigm(gi[H + j] + gh[H + j]);
    float n = tanhf(gi[2 * H + j] + r * gh[2 * H + j]);
    return (1.0f - z) * n + z * hprev[j];
}

// Warp-cooperative dot of one weight row (length K, 16B-aligned) with smem x.
template <int K>
__device__ __forceinline__ float warp_dot(const float* __restrict__ w,
                                          const float* __restrict__ x, int lane) {
    float a0 = 0.f, a1 = 0.f, a2 = 0.f, a3 = 0.f;
#pragma unroll
    for (int k0 = 0; k0 < K; k0 += 128) {
        int k = k0 + lane * 4;
        float4 f = *reinterpret_cast<const float4*>(w + k);
        float4 xv = *reinterpret_cast<const float4*>(x + k);
        a0 += f.x * xv.x; a1 += f.y * xv.y; a2 += f.z * xv.z; a3 += f.w * xv.w;
    }
    float acc = (a0 + a1) + (a2 + a3);
#pragma unroll
    for (int o = 16; o; o >>= 1) acc += __shfl_down_sync(0xffffffffu, acc, o);
    return acc;
}

// ---------------- K1: GRU0 gate matvecs -------------------------------------
// blocks [0,384): gi0 rows (Wih0, K=2H, x = [emb[tok], last_context])
// blocks [384,768): gh0 rows (Whh0, K=H, x = hidden[0])
__global__ void k_gates0(const int* __restrict__ tok,
                         const float* __restrict__ lastctx,
                         const float* __restrict__ hid,
                         const float* __restrict__ emb,
                         const float* __restrict__ Wih0, const float* __restrict__ bih0,
                         const float* __restrict__ Whh0, const float* __restrict__ bhh0) {
    __shared__ __align__(16) float sx[H2];
    int b = blockIdx.x;
    bool is_gi = (b < 384);
    if (is_gi) {
        int t = tok[0];
        for (int j = threadIdx.x; j < H2; j += 256)
            sx[j] = (j < H) ? emb[(size_t)t * H + j] : lastctx[j - H];
    } else {
        for (int j = threadIdx.x; j < H; j += 256) sx[j] = hid[j];
    }
    __syncthreads();
    int w = threadIdx.x >> 5, lane = threadIdx.x & 31;
    if (is_gi) {
        int row = b * 8 + w;
        float d = warp_dot<H2>(Wih0 + (size_t)row * H2, sx, lane);
        if (lane == 0) g_gi0[row] = d + bih0[row];
    } else {
        int row = (b - 384) * 8 + w;
        float d = warp_dot<H>(Whh0 + (size_t)row * H, sx, lane);
        if (lane == 0) g_gh0[row] = d + bhh0[row];
    }
}

// ---------------- K2: combine h0 + GRU1 gate matvecs -------------------------
// blocks [0,384): compute h0 (combine gates0) into smem, then gi1 rows (Wih1)
// blocks [384,768): gh1 rows (Whh1 with hidden[1])
// block 0 also: write h0 to new_hidden output; zero g_v
__global__ void k_gates1(const float* __restrict__ hid,
                         const float* __restrict__ Wih1, const float* __restrict__ bih1,
                         const float* __restrict__ Whh1, const float* __restrict__ bhh1,
                         float* __restrict__ out) {
    __shared__ __align__(16) float sx[H];
    int b = blockIdx.x;
    bool is_gi = (b < 384);
    if (is_gi) {
        for (int j = threadIdx.x; j < H; j += 256)
            sx[j] = gru_combine(g_gi0, g_gh0, hid, j);
    } else {
        for (int j = threadIdx.x; j < H; j += 256) sx[j] = hid[H + j];
    }
    __syncthreads();
    if (b == 0) {
        for (int j = threadIdx.x; j < H; j += 256) {
            out[OUT_NEWH + j] = sx[j];   // new_hidden[0]
            g_v[j] = 0.0f;               // zero for K3's atomics
        }
    }
    int w = threadIdx.x >> 5, lane = threadIdx.x & 31;
    if (is_gi) {
        int row = b * 8 + w;
        float d = warp_dot<H>(Wih1 + (size_t)row * H, sx, lane);
        if (lane == 0) g_gi1[row] = d + bih1[row];
    } else {
        int row = (b - 384) * 8 + w;
        float d = warp_dot<H>(Whh1 + (size_t)row * H, sx, lane);
        if (lane == 0) g_gh1[row] = d + bhh1[row];
    }
}

// ---------------- K3: v = h1 @ attn_W ----------------------------------------
// 64 blocks: 4 column groups x 16 row chunks. Each block rebuilds h1 (cheap).
// Block 0 also publishes h1 (scratch + new_hidden[1]).
// Note: attn_b folds into a softmax-invariant constant and is dropped.
__global__ void k_attnv(const float* __restrict__ hid,
                        const float* __restrict__ attnW,
                        float* __restrict__ out) {
    __shared__ __align__(16) float sh[H];
    for (int j = threadIdx.x; j < H; j += 256)
        sh[j] = gru_combine(g_gi1, g_gh1, hid + H, j);
    __syncthreads();
    if (blockIdx.x == 0) {
        for (int j = threadIdx.x; j < H; j += 256) {
            out[OUT_NEWH + H + j] = sh[j];   // new_hidden[1]
            g_h1[j] = sh[j];
        }
    }
    int colg = blockIdx.x & 3, rowc = blockIdx.x >> 2;
    int col = colg * 256 + threadIdx.x;
    int j0 = rowc * 64;
    float acc = 0.f;
#pragma unroll 8
    for (int j = j0; j < j0 + 64; ++j)
        acc += attnW[(size_t)j * H + col] * sh[j];
    atomicAdd(&g_v[col], acc);
}

// ---------------- K4: energies = enc @ v -------------------------------------
__global__ void k_energy(const float* __restrict__ enc) {
    __shared__ __align__(16) float sv[H];
    for (int j = threadIdx.x; j < H; j += 256) sv[j] = g_v[j];
    __syncthreads();
    int w = threadIdx.x >> 5, lane = threadIdx.x & 31;
    int row = blockIdx.x * 8 + w;
    float d = warp_dot<H>(enc + (size_t)row * H, sv, lane);
    if (lane == 0) g_energ[row] = d;
}

// ---------------- K5: softmax over S=4096 (one block) ------------------------
// Also writes attn_w output and zeroes g_ctx for K6.
__global__ void k_softmax(float* __restrict__ out) {
    __shared__ float sred[32];
    int tid = threadIdx.x;
    float e[4];
    float m = -1e30f;
#pragma unroll
    for (int i = 0; i < 4; i++) { e[i] = g_energ[tid + i * 1024]; m = fmaxf(m, e[i]); }
#pragma unroll
    for (int o = 16; o; o >>= 1) m = fmaxf(m, __shfl_xor_sync(0xffffffffu, m, o));
    if ((tid & 31) == 0) sred[tid >> 5] = m;
    __syncthreads();
    if (tid < 32) {
        float v = sred[tid];
#pragma unroll
        for (int o = 16; o; o >>= 1) v = fmaxf(v, __shfl_xor_sync(0xffffffffu, v, o));
        if (tid == 0) sred[0] = v;
    }
    __syncthreads();
    float M = sred[0];
    __syncthreads();
    float ex[4];
    float s = 0.f;
#pragma unroll
    for (int i = 0; i < 4; i++) { ex[i] = expf(e[i] - M); s += ex[i]; }
#pragma unroll
    for (int o = 16; o; o >>= 1) s += __shfl_xor_sync(0xffffffffu, s, o);
    if ((tid & 31) == 0) sred[tid >> 5] = s;
    __syncthreads();
    if (tid < 32) {
        float v = sred[tid];
#pragma unroll
        for (int o = 16; o; o >>= 1) v += __shfl_xor_sync(0xffffffffu, v, o);
        if (tid == 0) sred[0] = v;
    }
    __syncthreads();
    float inv = 1.0f / sred[0];
#pragma unroll
    for (int i = 0; i < 4; i++) {
        float wv = ex[i] * inv;
        g_attn[tid + i * 1024] = wv;
        out[OUT_ATTN + tid + i * 1024] = wv;
    }
    g_ctx[tid] = 0.0f;
}

// ---------------- K6: context = attn_w @ enc ---------------------------------
// 64 blocks: 4 column groups x 16 row chunks (256 rows each).
__global__ void k_context(const float* __restrict__ enc) {
    __shared__ float sw[256];
    int colg = blockIdx.x & 3, rowc = blockIdx.x >> 2;
    sw[threadIdx.x] = g_attn[rowc * 256 + threadIdx.x];
    __syncthreads();
    int col = colg * 256 + threadIdx.x;
    const float* base = enc + (size_t)(rowc * 256) * H + col;
    float acc = 0.f;
#pragma unroll 8
    for (int j = 0; j < 256; ++j) acc += sw[j] * base[(size_t)j * H];
    atomicAdd(&g_ctx[col], acc);
}

// ---------------- K7: logits = [h1, ctx] @ out_W^T + out_b -------------------
// 6283 blocks x 8 warps, one warp per vocab row. Each block also emits a
// (max, sum-exp) partial for the log-softmax. Block 0 copies ctx to output.
__global__ void k_logits(const float* __restrict__ outW,
                         const float* __restrict__ outb,
                         float* __restrict__ out) {
    __shared__ __align__(16) float sx[H2];
    __shared__ float srow[8];
    for (int j = threadIdx.x; j < H2; j += 256)
        sx[j] = (j < H) ? g_h1[j] : g_ctx[j - H];
    __syncthreads();
    if (blockIdx.x == 0) {
        for (int j = threadIdx.x; j < H; j += 256) out[OUT_CTX + j] = g_ctx[j];
    }
    int w = threadIdx.x >> 5, lane = threadIdx.x & 31;
    int row = blockIdx.x * 8 + w;
    float logit = -1e30f;
    if (row < V) {
        float d = warp_dot<H2>(outW + (size_t)row * H2, sx, lane);
        if (lane == 0) {
            logit = d + outb[row];
            g_logits[row] = logit;
        }
    }
    if (lane == 0) srow[w] = logit;
    __syncthreads();
    if (threadIdx.x == 0) {
        float m = -1e30f;
#pragma unroll
        for (int i = 0; i < 8; i++) m = fmaxf(m, srow[i]);
        float s = 0.f;
#pragma unroll
        for (int i = 0; i < 8; i++) s += expf(srow[i] - m);
        g_pm[blockIdx.x] = m;
        g_ps[blockIdx.x] = s;
    }
}

// ---------------- K8: combine partials -> global max + log-sum-exp -----------
__global__ void k_lse() {
    __shared__ float sred[32];
    int tid = threadIdx.x;
    float m = -1e30f;
    for (int i = tid; i < NB_LOGITS; i += 1024) m = fmaxf(m, g_pm[i]);
#pragma unroll
    for (int o = 16; o; o >>= 1) m = fmaxf(m, __shfl_xor_sync(0xffffffffu, m, o));
    if ((tid & 31) == 0) sred[tid >> 5] = m;
    __syncthreads();
    if (tid < 32) {
        float v = sred[tid];
#pragma unroll
        for (int o = 16; o; o >>= 1) v = fmaxf(v, __shfl_xor_sync(0xffffffffu, v, o));
        if (tid == 0) sred[0] = v;
    }
    __syncthreads();
    float M = sred[0];
    __syncthreads();
    float s = 0.f;
    for (int i = tid; i < NB_LOGITS; i += 1024) s += g_ps[i] * expf(g_pm[i] - M);
#pragma unroll
    for (int o = 16; o; o >>= 1) s += __shfl_xor_sync(0xffffffffu, s, o);
    if ((tid & 31) == 0) sred[tid >> 5] = s;
    __syncthreads();
    if (tid < 32) {
        float v = sred[tid];
#pragma unroll
        for (int o = 16; o; o >>= 1) v += __shfl_xor_sync(0xffffffffu, v, o);
        if (tid == 0) { g_red[0] = M; g_red[1] = logf(v); }
    }
}

// ---------------- K9: final log-softmax write --------------------------------
__global__ void k_final(float* __restrict__ out) {
    int i = blockIdx.x * 512 + threadIdx.x;
    if (i < V) out[OUT_LOGP + i] = g_logits[i] - g_red[0] - g_red[1];
}

// ---------------- launch -----------------------------------------------------
extern "C" void kernel_launch(void* const* d_in, const int* in_sizes, int n_in,
                              void* d_out, int out_size) {
    const int*   tok     = (const int*)d_in[0];
    const float* lastctx = (const float*)d_in[1];
    const float* hid     = (const float*)d_in[2];
    const float* enc     = (const float*)d_in[3];
    const float* emb     = (const float*)d_in[4];
    const float* attnW   = (const float*)d_in[5];
    // d_in[6] = attn_b: folds into a softmax-invariant constant; unused.
    const float* Wih0    = (const float*)d_in[7];
    const float* Whh0    = (const float*)d_in[8];
    const float* bih0    = (const float*)d_in[9];
    const float* bhh0    = (const float*)d_in[10];
    const float* Wih1    = (const float*)d_in[11];
    const float* Whh1    = (const float*)d_in[12];
    const float* bih1    = (const float*)d_in[13];
    const float* bhh1    = (const float*)d_in[14];
    const float* outW    = (const float*)d_in[15];
    const float* outb    = (const float*)d_in[16];
    float* out = (float*)d_out;

    k_gates0 <<<768, 256>>>(tok, lastctx, hid, emb, Wih0, bih0, Whh0, bhh0);
    k_gates1 <<<768, 256>>>(hid, Wih1, bih1, Whh1, bhh1, out);
    k_attnv  <<<64, 256>>>(hid, attnW, out);
    k_energy <<<512, 256>>>(enc);
    k_softmax<<<1, 1024>>>(out);
    k_context<<<64, 256>>>(enc);
    k_logits <<<NB_LOGITS, 256>>>(outW, outb, out);
    k_lse    <<<1, 1024>>>();
    k_final  <<<(V + 511) / 512, 512>>>(out);
}